// round 13
// baseline (speedup 1.0000x reference)
#include <cuda_runtime.h>
#include <cuda_fp16.h>
#include <cstdint>
#include <cstdio>
#include <math.h>

typedef unsigned int u32;

#define H    16
#define HD   64
#define MEMS 32768
#define IPQ  8
#define NCAND 16
#define BB   4
#define NN   512
#define DIN  1024
#define DOUT 1024
#define BNR  (BB*NN)
#define MOLD (MEMS - BNR)
#define SCALE 0.125f
#define LOSCALE 2048.0f
#define INV_LOSCALE (1.0f/2048.0f)

// ------------------------- scratch (device globals) -------------------------
__device__ float g_q  [BNR*DIN];
__device__ float g_k  [BNR*DIN];
__device__ float g_v  [BNR*DOUT];
__device__ float g_w  [BNR*DOUT];
__device__ float g_ao [BNR*DOUT];
__device__ float g_aom[BNR*DOUT];
__device__ float g_c1 [BNR*DOUT];
__device__ float g_c2 [BNR*DOUT];
__device__ float g_km [(size_t)BB*(NN*IPQ)*DIN];
__device__ float g_vm [(size_t)BB*(NN*IPQ)*DOUT];
__device__ int   g_idx [H*BNR*IPQ];
__device__ int   g_cand[(size_t)H*BNR*NCAND];
__device__ __half g_qhi[(size_t)H*BNR*HD];
__device__ __half g_khi[(size_t)H*MEMS*HD];
// split planes for tensor GEMM (lo stored x2048 to stay in fp16 normal range)
__device__ __half g_xhi[(size_t)BNR*DIN],  g_xlo[(size_t)BNR*DIN];
__device__ __half g_Whi[(size_t)5*DIN*DOUT], g_Wlo[(size_t)5*DIN*DOUT];
__device__ __half g_ahi[(size_t)BNR*DOUT], g_alo[(size_t)BNR*DOUT];

// ------------------------- helpers -------------------------
__device__ __forceinline__ u32 smem_u32(const void* p) {
    return (u32)__cvta_generic_to_shared(p);
}
__device__ __forceinline__ void ldsm_x4(u32 &r0, u32 &r1, u32 &r2, u32 &r3, u32 addr) {
    asm volatile("ldmatrix.sync.aligned.m8n8.x4.shared.b16 {%0,%1,%2,%3}, [%4];"
        : "=r"(r0), "=r"(r1), "=r"(r2), "=r"(r3) : "r"(addr));
}
__device__ __forceinline__ void ldsm_x2(u32 &r0, u32 &r1, u32 addr) {
    asm volatile("ldmatrix.sync.aligned.m8n8.x2.shared.b16 {%0,%1}, [%2];"
        : "=r"(r0), "=r"(r1) : "r"(addr));
}
__device__ __forceinline__ void mma_f16(float* c, u32 a0, u32 a1, u32 a2, u32 a3,
                                        u32 b0, u32 b1) {
    asm volatile("mma.sync.aligned.m16n8k16.row.col.f32.f16.f16.f32 "
        "{%0,%1,%2,%3}, {%4,%5,%6,%7}, {%8,%9}, {%0,%1,%2,%3};"
        : "+f"(c[0]), "+f"(c[1]), "+f"(c[2]), "+f"(c[3])
        : "r"(a0), "r"(a1), "r"(a2), "r"(a3), "r"(b0), "r"(b1));
}

// ------------------- fp32 -> fp16 hi + scaled lo split ----------------------
__global__ void split_f32(const float* __restrict__ src, __half* __restrict__ hi,
                          __half* __restrict__ lo)
{
    int e = blockIdx.x * 256 + threadIdx.x;
    float val = src[e];
    __half h = __float2half_rn(val);
    hi[e] = h;
    lo[e] = __float2half_rn((val - __half2float(h)) * LOSCALE);
}

// ------------------- split-fp16 HMMA GEMM: C = A * B^T ----------------------
// hi*hi -> acc; hi*lo' + lo'*hi -> acc2; C = acc + acc2/2048.
__global__ void __launch_bounds__(256)
hgemm_abt(const __half* __restrict__ Ahi, const __half* __restrict__ Alo,
          const __half* __restrict__ Bhi, const __half* __restrict__ Blo,
          float* __restrict__ C, int K,
          const float* __restrict__ bias, int do_sigmoid)
{
    extern __shared__ __half hsm[];
    __half* Ah = hsm;                 // [128][72]
    __half* Al = Ah + 128*72;
    __half* Bh = Al + 128*72;
    __half* Bl = Bh + 128*72;
    const u32 ALO_OFF = 128*72*2;
    const u32 BLO_OFF = 128*72*2;

    int t = threadIdx.x;
    int lane = t & 31, warp = t >> 5;
    int row0 = blockIdx.y * 128, col0 = blockIdx.x * 128;
    int mrow0 = (warp >> 1) * 32;
    int ncol0 = (warp & 1) * 64;

    float acc [2][8][4] = {};
    float acc2[2][8][4] = {};

    u32 a_base = smem_u32(&Ah[(mrow0 + (lane & 15))*72 + ((lane >> 4) & 1)*8]);
    u32 b_base = smem_u32(&Bh[(ncol0 + (lane & 7))*72 + ((lane >> 3) & 1)*8]);

    int lr = t >> 1, lc0 = (t & 1) * 32;

    for (int k0 = 0; k0 < K; k0 += 64) {
        {
            size_t asrc = (size_t)(row0 + lr)*K + k0 + lc0;
            #pragma unroll
            for (int uu = 0; uu < 4; uu++) {
                *(uint4*)&Ah[lr*72 + lc0 + uu*8] = *(const uint4*)&Ahi[asrc + uu*8];
            }
            #pragma unroll
            for (int uu = 0; uu < 4; uu++) {
                *(uint4*)&Al[lr*72 + lc0 + uu*8] = *(const uint4*)&Alo[asrc + uu*8];
            }
            size_t bsrc = (size_t)(col0 + lr)*K + k0 + lc0;
            #pragma unroll
            for (int uu = 0; uu < 4; uu++) {
                *(uint4*)&Bh[lr*72 + lc0 + uu*8] = *(const uint4*)&Bhi[bsrc + uu*8];
            }
            #pragma unroll
            for (int uu = 0; uu < 4; uu++) {
                *(uint4*)&Bl[lr*72 + lc0 + uu*8] = *(const uint4*)&Blo[bsrc + uu*8];
            }
        }
        __syncthreads();

        #pragma unroll
        for (int kc = 0; kc < 4; kc++) {
            u32 ah[2][4], al[2][4];
            #pragma unroll
            for (int mi = 0; mi < 2; mi++) {
                u32 aoff = a_base + (u32)mi*(16*72*2) + kc*32;
                ldsm_x4(ah[mi][0], ah[mi][1], ah[mi][2], ah[mi][3], aoff);
                ldsm_x4(al[mi][0], al[mi][1], al[mi][2], al[mi][3], aoff + ALO_OFF);
            }
            #pragma unroll
            for (int nj = 0; nj < 8; nj++) {
                u32 boff = b_base + (u32)nj*(8*72*2) + kc*32;
                u32 bh0, bh1, bl0, bl1;
                ldsm_x2(bh0, bh1, boff);
                ldsm_x2(bl0, bl1, boff + BLO_OFF);
                #pragma unroll
                for (int mi = 0; mi < 2; mi++) {
                    mma_f16(acc [mi][nj], ah[mi][0], ah[mi][1], ah[mi][2], ah[mi][3], bh0, bh1);
                    mma_f16(acc2[mi][nj], ah[mi][0], ah[mi][1], ah[mi][2], ah[mi][3], bl0, bl1);
                    mma_f16(acc2[mi][nj], al[mi][0], al[mi][1], al[mi][2], al[mi][3], bh0, bh1);
                }
            }
        }
        __syncthreads();
    }

    int gid = lane >> 2, tig = lane & 3;
    #pragma unroll
    for (int mi = 0; mi < 2; mi++) {
        #pragma unroll
        for (int nj = 0; nj < 8; nj++) {
            int r0 = row0 + mrow0 + mi*16 + gid;
            int cc = col0 + ncol0 + nj*8 + 2*tig;
            #pragma unroll
            for (int hh = 0; hh < 2; hh++) {
                int r = r0 + hh*8;
                float v0 = acc[mi][nj][hh*2+0] + acc2[mi][nj][hh*2+0]*INV_LOSCALE;
                float v1 = acc[mi][nj][hh*2+1] + acc2[mi][nj][hh*2+1]*INV_LOSCALE;
                if (bias) { v0 += bias[cc]; v1 += bias[cc+1]; }
                if (do_sigmoid) {
                    v0 = 1.0f / (1.0f + __expf(-v0));
                    v1 = 1.0f / (1.0f + __expf(-v1));
                }
                *(float2*)&C[(size_t)r * DOUT + cc] = make_float2(v0, v1);
            }
        }
    }
}

// ------------------- fp16 hi-plane precompute (sims) ------------------------
__global__ void convert_k(const float* __restrict__ kmem0)
{
    int e = blockIdx.x * 256 + threadIdx.x;
    int d = e & 63;
    int j = (e >> 6) & (MEMS - 1);
    int h = e >> 21;
    float val = (j < MOLD)
        ? kmem0[((size_t)h*MEMS + j + BNR)*HD + d]
        : g_k[(size_t)(j - MOLD)*DIN + h*HD + d];
    g_khi[e] = __float2half_rn(val);
}

__global__ void convert_q()
{
    int e = blockIdx.x * 256 + threadIdx.x;
    int d = e & 63;
    int r = (e >> 6) & (BNR - 1);
    int h = e >> 17;
    g_qhi[e] = __float2half_rn(g_q[(size_t)r*DIN + h*HD + d]);
}

// ------------------------- top-K push helpers -------------------------
__device__ __forceinline__ void tk_push8(float s, int id, float* tv, int* ti,
                                         float &tmin, int &tpos) {
    if (s > tmin) {
        tv[tpos] = s; ti[tpos] = id;
        tmin = tv[0]; tpos = 0;
        #pragma unroll
        for (int p = 1; p < 8; p++) {
            if (tv[p] < tmin) { tmin = tv[p]; tpos = p; }
        }
    }
}
__device__ __forceinline__ void tk_push16(float s, int id, float* tv, int* ti,
                                          float &tmin, int &tpos) {
    if (s > tmin) {
        tv[tpos] = s; ti[tpos] = id;
        tmin = tv[0]; tpos = 0;
        #pragma unroll
        for (int p = 1; p < 16; p++) {
            if (tv[p] < tmin) { tmin = tv[p]; tpos = p; }
        }
    }
}

// --------------- coarse sims + top-16 candidates via fp16 HMMA -------------
__global__ void __launch_bounds__(256, 2)
sims_topk()
{
    extern __shared__ char smraw[];
    __half* Qh = (__half*)smraw;                  // [64][72]
    __half* Kh = Qh + 64*72;                      // [128][72]
    float* Ss = (float*)(smraw + (64*72 + 128*72)*2);   // [64][132]

    int t = threadIdx.x;
    int h = blockIdx.y;
    int q0 = blockIdx.x * 64;
    int lane = t & 31, warp = t >> 5;
    int gid = lane >> 2, tig = lane & 3;

    {
        int r = t >> 2, c0 = (t & 3) * 16;
        size_t src = ((size_t)h*BNR + q0 + r)*HD + c0;
        *(uint4*)&Qh[r*72 + c0    ] = *(const uint4*)&g_qhi[src];
        *(uint4*)&Qh[r*72 + c0 + 8] = *(const uint4*)&g_qhi[src + 8];
    }

    float tv[8]; int ti[8];
    #pragma unroll
    for (int p = 0; p < 8; p++) { tv[p] = -INFINITY; ti[p] = 0; }
    float tmin = -INFINITY; int tpos = 0;

    int q0w = (warp >> 1) * 16;
    int kh0 = (warp & 1) * 64;

    u32 a_base = smem_u32(&Qh[(q0w + (lane & 15))*72 + ((lane >> 4) & 1)*8]);
    u32 b_base = smem_u32(&Kh[(kh0 + (lane & 7))*72 + ((lane >> 3) & 1)*8]);

    int qrow = t & 63, seg = t >> 6;
    int kr = t >> 1, kc0 = (t & 1) * 32;

    for (int tile = 0; tile < MEMS/128; tile++) {
        int j0 = tile * 128;
        {
            size_t src = ((size_t)h*MEMS + j0 + kr)*HD + kc0;
            #pragma unroll
            for (int uu = 0; uu < 4; uu++) {
                *(uint4*)&Kh[kr*72 + kc0 + uu*8] = *(const uint4*)&g_khi[src + uu*8];
            }
        }
        __syncthreads();

        float c8[8][4] = {};
        #pragma unroll
        for (int ks = 0; ks < 4; ks++) {
            u32 a0, a1, a2, a3;
            ldsm_x4(a0, a1, a2, a3, a_base + ks*32);
            #pragma unroll
            for (int j = 0; j < 8; j++) {
                u32 b0, b1;
                ldsm_x2(b0, b1, b_base + (u32)j*(8*72*2) + ks*32);
                mma_f16(c8[j], a0, a1, a2, a3, b0, b1);
            }
        }
        #pragma unroll
        for (int j = 0; j < 8; j++) {
            int col = kh0 + 8*j + 2*tig;
            *(float2*)&Ss[(q0w + gid    )*132 + col] = make_float2(c8[j][0], c8[j][1]);
            *(float2*)&Ss[(q0w + gid + 8)*132 + col] = make_float2(c8[j][2], c8[j][3]);
        }
        __syncthreads();

        const float4* srow = (const float4*)&Ss[qrow*132 + seg*32];
        int cb = j0 + seg*32;
        #pragma unroll
        for (int vv = 0; vv < 8; vv++) {
            float4 s4 = srow[vv];
            float m4 = fmaxf(fmaxf(s4.x, s4.y), fmaxf(s4.z, s4.w));
            if (m4 > tmin) {
                tk_push8(s4.x, cb + vv*4 + 0, tv, ti, tmin, tpos);
                tk_push8(s4.y, cb + vv*4 + 1, tv, ti, tmin, tpos);
                tk_push8(s4.z, cb + vv*4 + 2, tv, ti, tmin, tpos);
                tk_push8(s4.w, cb + vv*4 + 3, tv, ti, tmin, tpos);
            }
        }
    }
    __syncthreads();

    float* cval = Ss;
    int*   cidx = (int*)(Ss + 2048);
    #pragma unroll
    for (int p = 0; p < 8; p++) { cval[t*8 + p] = tv[p]; cidx[t*8 + p] = ti[p]; }
    __syncthreads();
    if (t < 64) {
        float fv[16]; int fi[16]; float fmin = -INFINITY; int fpos = 0;
        #pragma unroll
        for (int p = 0; p < 16; p++) { fv[p] = -INFINITY; fi[p] = 0; }
        for (int g = 0; g < 4; g++) {
            int src = t + g*64;
            #pragma unroll
            for (int p = 0; p < 8; p++) {
                tk_push16(cval[src*8 + p], cidx[src*8 + p], fv, fi, fmin, fpos);
            }
        }
        #pragma unroll
        for (int p = 0; p < 16; p++) {
            g_cand[((size_t)h*BNR + q0 + t)*NCAND + p] = fi[p];
        }
    }
}

// --------------- exact fp32 rescore of 16 candidates -> top-8 ---------------
__global__ void __launch_bounds__(256)
rescore_kernel(const float* __restrict__ kmem0)
{
    int e = blockIdx.x * 8 + (threadIdx.x >> 5);
    int lane = threadIdx.x & 31;
    int h = e >> 11, f = e & (BNR - 1);

    float s = -INFINITY;
    int myidx = -1;
    if (lane < NCAND) {
        myidx = g_cand[(size_t)e*NCAND + lane];
        const float* qrow = &g_q[(size_t)f*DIN + h*HD];
        const float* krow = (myidx < MOLD)
            ? &kmem0[((size_t)h*MEMS + myidx + BNR)*HD]
            : &g_k[(size_t)(myidx - MOLD)*DIN + h*HD];
        float acc = 0.0f;
        #pragma unroll
        for (int d4 = 0; d4 < 16; d4++) {
            float4 qv = *(const float4*)&qrow[d4*4];
            float4 kv = *(const float4*)&krow[d4*4];
            acc += qv.x*kv.x + qv.y*kv.y + qv.z*kv.z + qv.w*kv.w;
        }
        s = acc;
    }
    #pragma unroll
    for (int p = 0; p < IPQ; p++) {
        float m = s;
        #pragma unroll
        for (int o = 16; o >= 1; o >>= 1) {
            m = fmaxf(m, __shfl_xor_sync(0xffffffffu, m, o));
        }
        unsigned msk = __ballot_sync(0xffffffffu, s == m);
        int src = __ffs(msk) - 1;
        if (lane == src) {
            g_idx[(size_t)e*IPQ + p] = myidx;
            s = -INFINITY;
        }
    }
}

// --------------------- gather k_m / v_m from idx -----------------------------
__global__ void gather_kernel(const float* __restrict__ kmem0, const float* __restrict__ vmem0)
{
    int e = blockIdx.x * 256 + threadIdx.x;
    int c  = e & 1023;
    int m2 = (e >> 10) & 4095;
    int b  = e >> 22;
    int h = c >> 6, d = c & 63;
    int nq = m2 >> 3, ip = m2 & 7;
    int f = b * NN + nq;
    int row = g_idx[((size_t)h*BNR + f)*IPQ + ip];
    float kv, vv;
    if (row < MOLD) {
        size_t base = ((size_t)h*MEMS + row + BNR)*HD + d;
        kv = kmem0[base]; vv = vmem0[base];
    } else {
        int fl = row - MOLD;
        size_t base = (size_t)fl*DIN + h*HD + d;
        kv = g_k[base]; vv = g_v[base];
    }
    g_km[e] = kv;
    g_vm[e] = vv;
}

// ------------------- flash attention, 64-q tiles, parallel softmax ----------
__global__ void __launch_bounds__(256, 2)
flash_attn(const float* __restrict__ Qbuf, const float* __restrict__ Ksrc,
           const float* __restrict__ Vsrc, float* __restrict__ Obuf, int m)
{
    extern __shared__ float sm[];
    float* Qs_ = sm;                // 64*68
    float* Ks_ = Qs_ + 64*68;       // 64*68  (d-major)
    float* Vs_ = Ks_ + 64*68;       // 64*68
    float* Ss_ = Vs_ + 64*68;       // 64*68
    float* mrow = Ss_ + 64*68;
    float* lrow = mrow + 64;
    float* fac  = lrow + 64;

    int t = threadIdx.x;
    int b = blockIdx.z, h = blockIdx.y;
    int f0 = b * NN + blockIdx.x * 64;

    {
        int r = t >> 2, c0 = (t & 3) * 16;
        size_t src = (size_t)(f0 + r)*DIN + h*HD + c0;
        #pragma unroll
        for (int u = 0; u < 4; u++) {
            *(float4*)&Qs_[r*68 + c0 + u*4] = *(const float4*)&Qbuf[src + u*4];
        }
    }
    if (t < 64) { mrow[t] = -INFINITY; lrow[t] = 0.0f; }

    float o[4][4] = {};
    int qg = t >> 4, jg = t & 15;
    int qp = t >> 4, dp = (t & 15) * 4;
    int jrow = t & 63, jc0 = (t >> 6) * 16;
    __syncthreads();

    for (int j0 = 0; j0 < m; j0 += 64) {
        {
            size_t src = ((size_t)b*m + j0 + jrow)*DIN + h*HD + jc0;
            #pragma unroll
            for (int u = 0; u < 4; u++) {
                float4 kv = *(const float4*)&Ksrc[src + u*4];
                Ks_[(jc0 + u*4 + 0)*68 + jrow] = kv.x;
                Ks_[(jc0 + u*4 + 1)*68 + jrow] = kv.y;
                Ks_[(jc0 + u*4 + 2)*68 + jrow] = kv.z;
                Ks_[(jc0 + u*4 + 3)*68 + jrow] = kv.w;
            }
            #pragma unroll
            for (int u = 0; u < 4; u++) {
                *(float4*)&Vs_[jrow*68 + jc0 + u*4] = *(const float4*)&Vsrc[src + u*4];
            }
        }
        __syncthreads();

        float acc[4][4] = {};
        #pragma unroll
        for (int d4 = 0; d4 < 16; d4++) {
            float4 a0 = *(const float4*)&Qs_[(qg*4+0)*68 + d4*4];
            float4 a1 = *(const float4*)&Qs_[(qg*4+1)*68 + d4*4];
            float4 a2 = *(const float4*)&Qs_[(qg*4+2)*68 + d4*4];
            float4 a3 = *(const float4*)&Qs_[(qg*4+3)*68 + d4*4];
            #pragma unroll
            for (int dd = 0; dd < 4; dd++) {
                float4 bv = *(const float4*)&Ks_[(d4*4+dd)*68 + jg*4];
                float x0 = ((const float*)&a0)[dd];
                float x1 = ((const float*)&a1)[dd];
                float x2 = ((const float*)&a2)[dd];
                float x3 = ((const float*)&a3)[dd];
                acc[0][0] += x0*bv.x; acc[0][1] += x0*bv.y; acc[0][2] += x0*bv.z; acc[0][3] += x0*bv.w;
                acc[1][0] += x1*bv.x; acc[1][1] += x1*bv.y; acc[1][2] += x1*bv.z; acc[1][3] += x1*bv.w;
                acc[2][0] += x2*bv.x; acc[2][1] += x2*bv.y; acc[2][2] += x2*bv.z; acc[2][3] += x2*bv.w;
                acc[3][0] += x3*bv.x; acc[3][1] += x3*bv.y; acc[3][2] += x3*bv.z; acc[3][3] += x3*bv.w;
            }
        }

        #pragma unroll
        for (int i = 0; i < 4; i++) {
            int row = qg*4 + i;
            float s0 = acc[i][0]*SCALE, s1 = acc[i][1]*SCALE;
            float s2 = acc[i][2]*SCALE, s3 = acc[i][3]*SCALE;
            float rm = fmaxf(fmaxf(s0, s1), fmaxf(s2, s3));
            #pragma unroll
            for (int wdt = 1; wdt < 16; wdt <<= 1) {
                rm = fmaxf(rm, __shfl_xor_sync(0xffffffffu, rm, wdt, 16));
            }
            float mo = mrow[row];
            float mc = fmaxf(mo, rm);
            float fsc = __expf(mo - mc);
            float e0 = __expf(s0 - mc), e1 = __expf(s1 - mc);
            float e2 = __expf(s2 - mc), e3 = __expf(s3 - mc);
            float rs = e0 + e1 + e2 + e3;
            #pragma unroll
            for (int wdt = 1; wdt < 16; wdt <<= 1) {
                rs += __shfl_xor_sync(0xffffffffu, rs, wdt, 16);
            }
            float lold = lrow[row];
            mrow[row] = mc;
            lrow[row] = lold * fsc + rs;
            fac[row]  = fsc;
            *(float4*)&Ss_[row*68 + jg*4] = make_float4(e0, e1, e2, e3);
        }
        __syncthreads();

        // PV: 4q x 4d; j unrolled by 4 with broadcast float4 p loads
        float f0q = fac[qp*4+0], f1q = fac[qp*4+1];
        float f2q = fac[qp*4+2], f3q = fac[qp*4+3];
        #pragma unroll
        for (int u = 0; u < 4; u++) { o[0][u] *= f0q; o[1][u] *= f1q; o[2][u] *= f2q; o[3][u] *= f3q; }
        #pragma unroll 4
        for (int j4 = 0; j4 < 64; j4 += 4) {
            float4 pq0 = *(const float4*)&Ss_[(qp*4+0)*68 + j4];
            float4 pq1 = *(const float4*)&Ss_[(qp*4+1)*68 + j4];
            float4 pq2 = *(const float4*)&Ss_[(qp*4+2)*68 + j4];
            float4 pq3 = *(const float4*)&Ss_[(qp*4+3)*68 + j4];
            #pragma unroll
            for (int jj = 0; jj < 4; jj++) {
                float4 vv = *(const float4*)&Vs_[(j4+jj)*68 + dp];
                float p0 = ((const float*)&pq0)[jj];
                float p1 = ((const float*)&pq1)[jj];
                float p2 = ((const float*)&pq2)[jj];
                float p3 = ((const float*)&pq3)[jj];
                o[0][0] += p0*vv.x; o[0][1] += p0*vv.y; o[0][2] += p0*vv.z; o[0][3] += p0*vv.w;
                o[1][0] += p1*vv.x; o[1][1] += p1*vv.y; o[1][2] += p1*vv.z; o[1][3] += p1*vv.w;
                o[2][0] += p2*vv.x; o[2][1] += p2*vv.y; o[2][2] += p2*vv.z; o[2][3] += p2*vv.w;
                o[3][0] += p3*vv.x; o[3][1] += p3*vv.y; o[3][2] += p3*vv.z; o[3][3] += p3*vv.w;
            }
        }
        __syncthreads();
    }
    #pragma unroll
    for (int i = 0; i < 4; i++) {
        float inv = 1.0f / lrow[qp*4 + i];
        size_t dst = (size_t)(f0 + qp*4 + i)*DOUT + h*HD + dp;
        *(float4*)&Obuf[dst] = make_float4(o[i][0]*inv, o[i][1]*inv, o[i][2]*inv, o[i][3]*inv);
    }
}

// ---------------------------- gate combine -----------------------------------
__global__ void combine_kernel(float* __restrict__ out)
{
    int e = blockIdx.x * 256 + threadIdx.x;
    float w = g_w[e];
    out[e] = w * g_c1[e] + (1.0f - w) * g_c2[e];
}

// ------------------------------- launch --------------------------------------
extern "C" void kernel_launch(void* const* d_in, const int* in_sizes, int n_in,
                              void* d_out, int out_size)
{
    const float* x     = (const float*)d_in[0];
    const float* Wq    = (const float*)d_in[1];
    const float* Wk    = (const float*)d_in[2];
    const float* Wv    = (const float*)d_in[3];
    const float* Ww    = (const float*)d_in[4];
    const float* Wo    = (const float*)d_in[5];
    const float* bo    = (const float*)d_in[6];
    const float* kmem0 = (const float*)d_in[7];
    const float* vmem0 = (const float*)d_in[8];
    float* out = (float*)d_out;

    float *q, *k, *v, *w, *ao, *aom, *c1, *c2, *km, *vm;
    cudaGetSymbolAddress((void**)&q,   g_q);
    cudaGetSymbolAddress((void**)&k,   g_k);
    cudaGetSymbolAddress((void**)&v,   g_v);
    cudaGetSymbolAddress((void**)&w,   g_w);
    cudaGetSymbolAddress((void**)&ao,  g_ao);
    cudaGetSymbolAddress((void**)&aom, g_aom);
    cudaGetSymbolAddress((void**)&c1,  g_c1);
    cudaGetSymbolAddress((void**)&c2,  g_c2);
    cudaGetSymbolAddress((void**)&km,  g_km);
    cudaGetSymbolAddress((void**)&vm,  g_vm);
    __half *xhi, *xlo, *Whi, *Wlo, *ahi, *alo;
    cudaGetSymbolAddress((void**)&xhi, g_xhi);
    cudaGetSymbolAddress((void**)&xlo, g_xlo);
    cudaGetSymbolAddress((void**)&Whi, g_Whi);
    cudaGetSymbolAddress((void**)&Wlo, g_Wlo);
    cudaGetSymbolAddress((void**)&ahi, g_ahi);
    cudaGetSymbolAddress((void**)&alo, g_alo);

    const int SIMS_SMEM  = (64*72 + 128*72)*2 + 64*132*4;   // 61440
    const int FLASH_SMEM = (4*64*68 + 3*64)*4;              // 70400
    const int HGEMM_SMEM = 4*128*72*2;                      // 73728
    cudaFuncSetAttribute(sims_topk,  cudaFuncAttributeMaxDynamicSharedMemorySize, SIMS_SMEM);
    cudaFuncSetAttribute(flash_attn, cudaFuncAttributeMaxDynamicSharedMemorySize, FLASH_SMEM);
    cudaFuncSetAttribute(hgemm_abt,  cudaFuncAttributeMaxDynamicSharedMemorySize, HGEMM_SMEM);

    const int WSZ = DIN*DOUT;
    dim3 hgrid(DOUT/128, BNR/128);

    split_f32<<<(BNR*DIN)/256, 256>>>(x,  xhi, xlo);
    split_f32<<<WSZ/256, 256>>>(Wq, Whi + 0*WSZ, Wlo + 0*WSZ);
    split_f32<<<WSZ/256, 256>>>(Wk, Whi + 1*WSZ, Wlo + 1*WSZ);
    split_f32<<<WSZ/256, 256>>>(Wv, Whi + 2*WSZ, Wlo + 2*WSZ);
    split_f32<<<WSZ/256, 256>>>(Ww, Whi + 3*WSZ, Wlo + 3*WSZ);
    split_f32<<<WSZ/256, 256>>>(Wo, Whi + 4*WSZ, Wlo + 4*WSZ);

    hgemm_abt<<<hgrid, 256, HGEMM_SMEM>>>(xhi, xlo, Whi + 0*WSZ, Wlo + 0*WSZ, q, DIN, 0, 0);
    hgemm_abt<<<hgrid, 256, HGEMM_SMEM>>>(xhi, xlo, Whi + 1*WSZ, Wlo + 1*WSZ, k, DIN, 0, 0);
    hgemm_abt<<<hgrid, 256, HGEMM_SMEM>>>(xhi, xlo, Whi + 2*WSZ, Wlo + 2*WSZ, v, DIN, 0, 0);
    hgemm_abt<<<hgrid, 256, HGEMM_SMEM>>>(xhi, xlo, Whi + 3*WSZ, Wlo + 3*WSZ, w, DIN, 0, 1);

    convert_q<<<(H*BNR*HD)/256, 256>>>();
    convert_k<<<(H*MEMS*HD)/256, 256>>>(kmem0);

    sims_topk<<<dim3(BNR/64, H), 256, SIMS_SMEM>>>();
    flash_attn<<<dim3(NN/64, H, BB), 256, FLASH_SMEM>>>(q, k, v, ao, NN);
    rescore_kernel<<<(H*BNR)/8, 256>>>(kmem0);
    gather_kernel<<<(BB*NN*IPQ*DIN)/256, 256>>>(kmem0, vmem0);
    flash_attn<<<dim3(NN/64, H, BB), 256, FLASH_SMEM>>>(q, km, vm, aom, NN*IPQ);

    split_f32<<<(BNR*DOUT)/256, 256>>>(ao, ahi, alo);
    hgemm_abt<<<hgrid, 256, HGEMM_SMEM>>>(ahi, alo, Whi + 4*WSZ, Wlo + 4*WSZ, c1, DOUT, bo, 0);
    split_f32<<<(BNR*DOUT)/256, 256>>>(aom, ahi, alo);
    hgemm_abt<<<hgrid, 256, HGEMM_SMEM>>>(ahi, alo, Whi + 4*WSZ, Wlo + 4*WSZ, c2, DOUT, bo, 0);

    combine_kernel<<<(BNR*DOUT)/256, 256>>>(out);
}

// round 17
// speedup vs baseline: 1.1007x; 1.1007x over previous
#include <cuda_runtime.h>
#include <cuda_fp16.h>
#include <cstdint>
#include <cstdio>
#include <math.h>

typedef unsigned int u32;

#define H    16
#define HD   64
#define MEMS 32768
#define IPQ  8
#define NCAND 16
#define BB   4
#define NN   512
#define DIN  1024
#define DOUT 1024
#define BNR  (BB*NN)
#define MOLD (MEMS - BNR)
#define SCALE 0.125f
#define LOSCALE 2048.0f
#define INV_LOSCALE (1.0f/2048.0f)

// ------------------------- scratch (device globals) -------------------------
__device__ float g_q  [BNR*DIN];
__device__ float g_k  [BNR*DIN];
__device__ float g_v  [BNR*DOUT];
__device__ float g_w  [BNR*DOUT];
__device__ float g_ao [BNR*DOUT];
__device__ float g_aom[BNR*DOUT];
__device__ float g_c1 [BNR*DOUT];
__device__ float g_c2 [BNR*DOUT];
__device__ float g_km [(size_t)BB*(NN*IPQ)*DIN];
__device__ float g_vm [(size_t)BB*(NN*IPQ)*DOUT];
__device__ int   g_idx [H*BNR*IPQ];
__device__ int   g_cand[(size_t)H*BNR*NCAND];
__device__ __half g_qhi[(size_t)H*BNR*HD];
__device__ __half g_khi[(size_t)H*MEMS*HD];
__device__ __half g_xhi[(size_t)BNR*DIN],  g_xlo[(size_t)BNR*DIN];
__device__ __half g_Whi[(size_t)5*DIN*DOUT], g_Wlo[(size_t)5*DIN*DOUT];
__device__ __half g_ahi[(size_t)BNR*DOUT], g_alo[(size_t)BNR*DOUT];

// ------------------------- helpers -------------------------
__device__ __forceinline__ u32 smem_u32(const void* p) {
    return (u32)__cvta_generic_to_shared(p);
}
__device__ __forceinline__ void ldsm_x4(u32 &r0, u32 &r1, u32 &r2, u32 &r3, u32 addr) {
    asm volatile("ldmatrix.sync.aligned.m8n8.x4.shared.b16 {%0,%1,%2,%3}, [%4];"
        : "=r"(r0), "=r"(r1), "=r"(r2), "=r"(r3) : "r"(addr));
}
__device__ __forceinline__ void ldsm_x2(u32 &r0, u32 &r1, u32 addr) {
    asm volatile("ldmatrix.sync.aligned.m8n8.x2.shared.b16 {%0,%1}, [%2];"
        : "=r"(r0), "=r"(r1) : "r"(addr));
}
__device__ __forceinline__ void mma_f16(float* c, u32 a0, u32 a1, u32 a2, u32 a3,
                                        u32 b0, u32 b1) {
    asm volatile("mma.sync.aligned.m16n8k16.row.col.f32.f16.f16.f32 "
        "{%0,%1,%2,%3}, {%4,%5,%6,%7}, {%8,%9}, {%0,%1,%2,%3};"
        : "+f"(c[0]), "+f"(c[1]), "+f"(c[2]), "+f"(c[3])
        : "r"(a0), "r"(a1), "r"(a2), "r"(a3), "r"(b0), "r"(b1));
}

// ------------------- fp32 -> fp16 hi + scaled lo split ----------------------
__global__ void split_f32(const float* __restrict__ src, __half* __restrict__ hi,
                          __half* __restrict__ lo)
{
    int e = blockIdx.x * 256 + threadIdx.x;
    float val = src[e];
    __half h = __float2half_rn(val);
    hi[e] = h;
    lo[e] = __float2half_rn((val - __half2float(h)) * LOSCALE);
}

// ------------------- split-fp16 HMMA GEMM: C = A * B^T ----------------------
__global__ void __launch_bounds__(256)
hgemm_abt(const __half* __restrict__ Ahi, const __half* __restrict__ Alo,
          const __half* __restrict__ Bhi, const __half* __restrict__ Blo,
          float* __restrict__ C, int K,
          const float* __restrict__ bias, int do_sigmoid)
{
    extern __shared__ __half hsm[];
    __half* Ah = hsm;                 // [128][72]
    __half* Al = Ah + 128*72;
    __half* Bh = Al + 128*72;
    __half* Bl = Bh + 128*72;
    const u32 ALO_OFF = 128*72*2;
    const u32 BLO_OFF = 128*72*2;

    int t = threadIdx.x;
    int lane = t & 31, warp = t >> 5;
    int row0 = blockIdx.y * 128, col0 = blockIdx.x * 128;
    int mrow0 = (warp >> 1) * 32;
    int ncol0 = (warp & 1) * 64;

    float acc [2][8][4] = {};
    float acc2[2][8][4] = {};

    u32 a_base = smem_u32(&Ah[(mrow0 + (lane & 15))*72 + ((lane >> 4) & 1)*8]);
    u32 b_base = smem_u32(&Bh[(ncol0 + (lane & 7))*72 + ((lane >> 3) & 1)*8]);

    int lr = t >> 1, lc0 = (t & 1) * 32;

    for (int k0 = 0; k0 < K; k0 += 64) {
        {
            size_t asrc = (size_t)(row0 + lr)*K + k0 + lc0;
            #pragma unroll
            for (int uu = 0; uu < 4; uu++) {
                *(uint4*)&Ah[lr*72 + lc0 + uu*8] = *(const uint4*)&Ahi[asrc + uu*8];
            }
            #pragma unroll
            for (int uu = 0; uu < 4; uu++) {
                *(uint4*)&Al[lr*72 + lc0 + uu*8] = *(const uint4*)&Alo[asrc + uu*8];
            }
            size_t bsrc = (size_t)(col0 + lr)*K + k0 + lc0;
            #pragma unroll
            for (int uu = 0; uu < 4; uu++) {
                *(uint4*)&Bh[lr*72 + lc0 + uu*8] = *(const uint4*)&Bhi[bsrc + uu*8];
            }
            #pragma unroll
            for (int uu = 0; uu < 4; uu++) {
                *(uint4*)&Bl[lr*72 + lc0 + uu*8] = *(const uint4*)&Blo[bsrc + uu*8];
            }
        }
        __syncthreads();

        #pragma unroll
        for (int kc = 0; kc < 4; kc++) {
            u32 ah[2][4], al[2][4];
            #pragma unroll
            for (int mi = 0; mi < 2; mi++) {
                u32 aoff = a_base + (u32)mi*(16*72*2) + kc*32;
                ldsm_x4(ah[mi][0], ah[mi][1], ah[mi][2], ah[mi][3], aoff);
                ldsm_x4(al[mi][0], al[mi][1], al[mi][2], al[mi][3], aoff + ALO_OFF);
            }
            #pragma unroll
            for (int nj = 0; nj < 8; nj++) {
                u32 boff = b_base + (u32)nj*(8*72*2) + kc*32;
                u32 bh0, bh1, bl0, bl1;
                ldsm_x2(bh0, bh1, boff);
                ldsm_x2(bl0, bl1, boff + BLO_OFF);
                #pragma unroll
                for (int mi = 0; mi < 2; mi++) {
                    mma_f16(acc [mi][nj], ah[mi][0], ah[mi][1], ah[mi][2], ah[mi][3], bh0, bh1);
                    mma_f16(acc2[mi][nj], ah[mi][0], ah[mi][1], ah[mi][2], ah[mi][3], bl0, bl1);
                    mma_f16(acc2[mi][nj], al[mi][0], al[mi][1], al[mi][2], al[mi][3], bh0, bh1);
                }
            }
        }
        __syncthreads();
    }

    int gid = lane >> 2, tig = lane & 3;
    #pragma unroll
    for (int mi = 0; mi < 2; mi++) {
        #pragma unroll
        for (int nj = 0; nj < 8; nj++) {
            int r0 = row0 + mrow0 + mi*16 + gid;
            int cc = col0 + ncol0 + nj*8 + 2*tig;
            #pragma unroll
            for (int hh = 0; hh < 2; hh++) {
                int r = r0 + hh*8;
                float v0 = acc[mi][nj][hh*2+0] + acc2[mi][nj][hh*2+0]*INV_LOSCALE;
                float v1 = acc[mi][nj][hh*2+1] + acc2[mi][nj][hh*2+1]*INV_LOSCALE;
                if (bias) { v0 += bias[cc]; v1 += bias[cc+1]; }
                if (do_sigmoid) {
                    v0 = 1.0f / (1.0f + __expf(-v0));
                    v1 = 1.0f / (1.0f + __expf(-v1));
                }
                *(float2*)&C[(size_t)r * DOUT + cc] = make_float2(v0, v1);
            }
        }
    }
}

// ------------------- fp16 hi-plane precompute (sims) ------------------------
__global__ void convert_k(const float* __restrict__ kmem0)
{
    int e4 = blockIdx.x * 256 + threadIdx.x;
    int d4 = e4 & 15;
    int j  = (e4 >> 4) & (MEMS - 1);
    int h  = e4 >> 19;
    float4 v;
    if (j < MOLD) v = *(const float4*)&kmem0[((size_t)h*MEMS + j + BNR)*HD + d4*4];
    else          v = *(const float4*)&g_k[(size_t)(j - MOLD)*DIN + h*HD + d4*4];
    __half2* dst = (__half2*)&g_khi[(size_t)e4*4];
    dst[0] = __floats2half2_rn(v.x, v.y);
    dst[1] = __floats2half2_rn(v.z, v.w);
}

__global__ void convert_q()
{
    int e = blockIdx.x * 256 + threadIdx.x;
    int d = e & 63;
    int r = (e >> 6) & (BNR - 1);
    int h = e >> 17;
    g_qhi[e] = __float2half_rn(g_q[(size_t)r*DIN + h*HD + d]);
}

// ------------------------- top-K push helpers -------------------------
__device__ __forceinline__ void tk_push8(float s, int id, float* tv, int* ti,
                                         float &tmin, int &tpos) {
    if (s > tmin) {
        tv[tpos] = s; ti[tpos] = id;
        tmin = tv[0]; tpos = 0;
        #pragma unroll
        for (int p = 1; p < 8; p++) {
            if (tv[p] < tmin) { tmin = tv[p]; tpos = p; }
        }
    }
}
__device__ __forceinline__ void tk_push16(float s, int id, float* tv, int* ti,
                                          float &tmin, int &tpos) {
    if (s > tmin) {
        tv[tpos] = s; ti[tpos] = id;
        tmin = tv[0]; tpos = 0;
        #pragma unroll
        for (int p = 1; p < 16; p++) {
            if (tv[p] < tmin) { tmin = tv[p]; tpos = p; }
        }
    }
}

// --------------- coarse sims + top-16 candidates via fp16 HMMA -------------
__global__ void __launch_bounds__(256, 2)
sims_topk()
{
    extern __shared__ char smraw[];
    __half* Qh = (__half*)smraw;                  // [64][72]
    __half* Kh = Qh + 64*72;                      // [128][72]
    float* Ss = (float*)(smraw + (64*72 + 128*72)*2);   // [64][132]

    int t = threadIdx.x;
    int h = blockIdx.y;
    int q0 = blockIdx.x * 64;
    int lane = t & 31, warp = t >> 5;
    int gid = lane >> 2, tig = lane & 3;

    {
        int r = t >> 2, c0 = (t & 3) * 16;
        size_t src = ((size_t)h*BNR + q0 + r)*HD + c0;
        *(uint4*)&Qh[r*72 + c0    ] = *(const uint4*)&g_qhi[src];
        *(uint4*)&Qh[r*72 + c0 + 8] = *(const uint4*)&g_qhi[src + 8];
    }

    float tv[8]; int ti[8];
    #pragma unroll
    for (int p = 0; p < 8; p++) { tv[p] = -INFINITY; ti[p] = 0; }
    float tmin = -INFINITY; int tpos = 0;

    int q0w = (warp >> 1) * 16;
    int kh0 = (warp & 1) * 64;

    u32 a_base = smem_u32(&Qh[(q0w + (lane & 15))*72 + ((lane >> 4) & 1)*8]);
    u32 b_base = smem_u32(&Kh[(kh0 + (lane & 7))*72 + ((lane >> 3) & 1)*8]);

    int qrow = t & 63, seg = t >> 6;
    int kr = t >> 1, kc0 = (t & 1) * 32;

    for (int tile = 0; tile < MEMS/128; tile++) {
        int j0 = tile * 128;
        {
            size_t src = ((size_t)h*MEMS + j0 + kr)*HD + kc0;
            #pragma unroll
            for (int uu = 0; uu < 4; uu++) {
                *(uint4*)&Kh[kr*72 + kc0 + uu*8] = *(const uint4*)&g_khi[src + uu*8];
            }
        }
        __syncthreads();

        float c8[8][4] = {};
        #pragma unroll
        for (int ks = 0; ks < 4; ks++) {
            u32 a0, a1, a2, a3;
            ldsm_x4(a0, a1, a2, a3, a_base + ks*32);
            #pragma unroll
            for (int j = 0; j < 8; j++) {
                u32 b0, b1;
                ldsm_x2(b0, b1, b_base + (u32)j*(8*72*2) + ks*32);
                mma_f16(c8[j], a0, a1, a2, a3, b0, b1);
            }
        }
        #pragma unroll
        for (int j = 0; j < 8; j++) {
            int col = kh0 + 8*j + 2*tig;
            *(float2*)&Ss[(q0w + gid    )*132 + col] = make_float2(c8[j][0], c8[j][1]);
            *(float2*)&Ss[(q0w + gid + 8)*132 + col] = make_float2(c8[j][2], c8[j][3]);
        }
        __syncthreads();

        const float4* srow = (const float4*)&Ss[qrow*132 + seg*32];
        int cb = j0 + seg*32;
        #pragma unroll
        for (int vv = 0; vv < 8; vv++) {
            float4 s4 = srow[vv];
            float m4 = fmaxf(fmaxf(s4.x, s4.y), fmaxf(s4.z, s4.w));
            if (m4 > tmin) {
                tk_push8(s4.x, cb + vv*4 + 0, tv, ti, tmin, tpos);
                tk_push8(s4.y, cb + vv*4 + 1, tv, ti, tmin, tpos);
                tk_push8(s4.z, cb + vv*4 + 2, tv, ti, tmin, tpos);
                tk_push8(s4.w, cb + vv*4 + 3, tv, ti, tmin, tpos);
            }
        }
    }
    __syncthreads();

    float* cval = Ss;
    int*   cidx = (int*)(Ss + 2048);
    #pragma unroll
    for (int p = 0; p < 8; p++) { cval[t*8 + p] = tv[p]; cidx[t*8 + p] = ti[p]; }
    __syncthreads();
    if (t < 64) {
        float fv[16]; int fi[16]; float fmin = -INFINITY; int fpos = 0;
        #pragma unroll
        for (int p = 0; p < 16; p++) { fv[p] = -INFINITY; fi[p] = 0; }
        for (int g = 0; g < 4; g++) {
            int src = t + g*64;
            #pragma unroll
            for (int p = 0; p < 8; p++) {
                tk_push16(cval[src*8 + p], cidx[src*8 + p], fv, fi, fmin, fpos);
            }
        }
        #pragma unroll
        for (int p = 0; p < 16; p++) {
            g_cand[((size_t)h*BNR + q0 + t)*NCAND + p] = fi[p];
        }
    }
}

// --------------- exact fp32 rescore of 16 candidates -> top-8 ---------------
__global__ void __launch_bounds__(256)
rescore_kernel(const float* __restrict__ kmem0)
{
    int e = blockIdx.x * 8 + (threadIdx.x >> 5);
    int lane = threadIdx.x & 31;
    int h = e >> 11, f = e & (BNR - 1);

    float s = -INFINITY;
    int myidx = -1;
    if (lane < NCAND) {
        myidx = g_cand[(size_t)e*NCAND + lane];
        const float* qrow = &g_q[(size_t)f*DIN + h*HD];
        const float* krow = (myidx < MOLD)
            ? &kmem0[((size_t)h*MEMS + myidx + BNR)*HD]
            : &g_k[(size_t)(myidx - MOLD)*DIN + h*HD];
        float acc = 0.0f;
        #pragma unroll
        for (int d4 = 0; d4 < 16; d4++) {
            float4 qv = *(const float4*)&qrow[d4*4];
            float4 kv = *(const float4*)&krow[d4*4];
            acc += qv.x*kv.x + qv.y*kv.y + qv.z*kv.z + qv.w*kv.w;
        }
        s = acc;
    }
    #pragma unroll
    for (int p = 0; p < IPQ; p++) {
        float m = s;
        #pragma unroll
        for (int o = 16; o >= 1; o >>= 1) {
            m = fmaxf(m, __shfl_xor_sync(0xffffffffu, m, o));
        }
        unsigned msk = __ballot_sync(0xffffffffu, s == m);
        int src = __ffs(msk) - 1;
        if (lane == src) {
            g_idx[(size_t)e*IPQ + p] = myidx;
            s = -INFINITY;
        }
    }
}

// --------------------- gather k_m / v_m from idx -----------------------------
__global__ void gather_kernel(const float* __restrict__ kmem0, const float* __restrict__ vmem0)
{
    int e = blockIdx.x * 256 + threadIdx.x;
    int c  = e & 1023;
    int m2 = (e >> 10) & 4095;
    int b  = e >> 22;
    int h = c >> 6, d = c & 63;
    int nq = m2 >> 3, ip = m2 & 7;
    int f = b * NN + nq;
    int row = g_idx[((size_t)h*BNR + f)*IPQ + ip];
    float kv, vv;
    if (row < MOLD) {
        size_t base = ((size_t)h*MEMS + row + BNR)*HD + d;
        kv = kmem0[base]; vv = vmem0[base];
    } else {
        int fl = row - MOLD;
        size_t base = (size_t)fl*DIN + h*HD + d;
        kv = g_k[base]; vv = g_v[base];
    }
    g_km[e] = kv;
    g_vm[e] = vv;
}

// ---------- flash attention: QK via split-fp16 HMMA, fp32 softmax/PV --------
// smem: Qh/Ql [64][72] f16, Kh/Kl [64][72] f16, Vs [64][68] f32, Ss [64][68] f32.
__global__ void __launch_bounds__(256, 2)
flash_attn(const float* __restrict__ Qbuf, const float* __restrict__ Ksrc,
           const float* __restrict__ Vsrc, float* __restrict__ Obuf, int m)
{
    extern __shared__ char fsm[];
    __half* Qh = (__half*)fsm;            // [64][72]
    __half* Ql = Qh + 64*72;
    __half* Kh = Ql + 64*72;              // [64][72]
    __half* Kl = Kh + 64*72;
    float* Vs_ = (float*)(fsm + 4*64*72*2);   // 64*68
    float* Ss_ = Vs_ + 64*68;                 // 64*68
    float* mrow = Ss_ + 64*68;
    float* lrow = mrow + 64;
    float* fac  = lrow + 64;
    const u32 QLO_OFF = 64*72*2;
    const u32 KLO_OFF = 64*72*2;

    int t = threadIdx.x;
    int lane = t & 31, warp = t >> 5;
    int b = blockIdx.z, h = blockIdx.y;
    int f0 = b * NN + blockIdx.x * 64;

    // load Q tile -> fp16 hi/lo planes
    {
        int r = t >> 2, c0 = (t & 3) * 16;
        size_t src = (size_t)(f0 + r)*DIN + h*HD + c0;
        #pragma unroll
        for (int u = 0; u < 4; u++) {
            float4 qv = *(const float4*)&Qbuf[src + u*4];
            __half2 h0 = __floats2half2_rn(qv.x, qv.y);
            __half2 h1 = __floats2half2_rn(qv.z, qv.w);
            *(__half2*)&Qh[r*72 + c0 + u*4    ] = h0;
            *(__half2*)&Qh[r*72 + c0 + u*4 + 2] = h1;
            float lx = (qv.x - __half2float(h0.x)) * LOSCALE;
            float ly = (qv.y - __half2float(h0.y)) * LOSCALE;
            float lz = (qv.z - __half2float(h1.x)) * LOSCALE;
            float lw = (qv.w - __half2float(h1.y)) * LOSCALE;
            *(__half2*)&Ql[r*72 + c0 + u*4    ] = __floats2half2_rn(lx, ly);
            *(__half2*)&Ql[r*72 + c0 + u*4 + 2] = __floats2half2_rn(lz, lw);
        }
    }
    if (t < 64) { mrow[t] = -INFINITY; lrow[t] = 0.0f; }

    float o[4][4] = {};
    int qg = t >> 4, jg = t & 15;
    int qp = t >> 4, dp = (t & 15) * 4;
    int jrow = t & 63, jc0 = (t >> 6) * 16;
    int gid = lane >> 2, tig = lane & 3;
    int q0w = (warp >> 1) * 16;       // warp q-strip (4 strips of 16)
    int jh0 = (warp & 1) * 32;        // warp j-half

    u32 a_base = smem_u32(&Qh[(q0w + (lane & 15))*72 + ((lane >> 4) & 1)*8]);
    u32 b_base = smem_u32(&Kh[(jh0 + (lane & 7))*72 + ((lane >> 3) & 1)*8]);
    __syncthreads();

    for (int j0 = 0; j0 < m; j0 += 64) {
        // load K -> fp16 hi/lo; V fp32
        {
            size_t src = ((size_t)b*m + j0 + jrow)*DIN + h*HD + jc0;
            #pragma unroll
            for (int u = 0; u < 4; u++) {
                float4 kv = *(const float4*)&Ksrc[src + u*4];
                __half2 h0 = __floats2half2_rn(kv.x, kv.y);
                __half2 h1 = __floats2half2_rn(kv.z, kv.w);
                *(__half2*)&Kh[jrow*72 + jc0 + u*4    ] = h0;
                *(__half2*)&Kh[jrow*72 + jc0 + u*4 + 2] = h1;
                float lx = (kv.x - __half2float(h0.x)) * LOSCALE;
                float ly = (kv.y - __half2float(h0.y)) * LOSCALE;
                float lz = (kv.z - __half2float(h1.x)) * LOSCALE;
                float lw = (kv.w - __half2float(h1.y)) * LOSCALE;
                *(__half2*)&Kl[jrow*72 + jc0 + u*4    ] = __floats2half2_rn(lx, ly);
                *(__half2*)&Kl[jrow*72 + jc0 + u*4 + 2] = __floats2half2_rn(lz, lw);
                *(float4*)&Vs_[jrow*68 + jc0 + u*4] = *(const float4*)&Vsrc[src + u*4];
            }
        }
        __syncthreads();

        // QK via split HMMA: warp computes 16q x 32j
        {
            float c8[4][4] = {};
            float c82[4][4] = {};
            #pragma unroll
            for (int ks = 0; ks < 4; ks++) {
                u32 ah0, ah1, ah2, ah3, al0, al1, al2, al3;
                ldsm_x4(ah0, ah1, ah2, ah3, a_base + ks*32);
                ldsm_x4(al0, al1, al2, al3, a_base + QLO_OFF + ks*32);
                #pragma unroll
                for (int nj = 0; nj < 4; nj++) {
                    u32 boff = b_base + (u32)nj*(8*72*2) + ks*32;
                    u32 bh0, bh1, bl0, bl1;
                    ldsm_x2(bh0, bh1, boff);
                    ldsm_x2(bl0, bl1, boff + KLO_OFF);
                    mma_f16(c8 [nj], ah0, ah1, ah2, ah3, bh0, bh1);
                    mma_f16(c82[nj], ah0, ah1, ah2, ah3, bl0, bl1);
                    mma_f16(c82[nj], al0, al1, al2, al3, bh0, bh1);
                }
            }
            #pragma unroll
            for (int nj = 0; nj < 4; nj++) {
                int col = jh0 + nj*8 + 2*tig;
                float v0 = (c8[nj][0] + c82[nj][0]*INV_LOSCALE) * SCALE;
                float v1 = (c8[nj][1] + c82[nj][1]*INV_LOSCALE) * SCALE;
                float v2 = (c8[nj][2] + c82[nj][2]*INV_LOSCALE) * SCALE;
                float v3 = (c8[nj][3] + c82[nj][3]*INV_LOSCALE) * SCALE;
                *(float2*)&Ss_[(q0w + gid    )*68 + col] = make_float2(v0, v1);
                *(float2*)&Ss_[(q0w + gid + 8)*68 + col] = make_float2(v2, v3);
            }
        }
        __syncthreads();

        // parallel online softmax (16 lanes per row over jg)
        #pragma unroll
        for (int i = 0; i < 4; i++) {
            int row = qg*4 + i;
            float4 s4 = *(const float4*)&Ss_[row*68 + jg*4];
            float rm = fmaxf(fmaxf(s4.x, s4.y), fmaxf(s4.z, s4.w));
            #pragma unroll
            for (int wdt = 1; wdt < 16; wdt <<= 1) {
                rm = fmaxf(rm, __shfl_xor_sync(0xffffffffu, rm, wdt, 16));
            }
            float mo = mrow[row];
            float mc = fmaxf(mo, rm);
            float fsc = __expf(mo - mc);
            float e0 = __expf(s4.x - mc), e1 = __expf(s4.y - mc);
            float e2 = __expf(s4.z - mc), e3 = __expf(s4.w - mc);
            float rs = e0 + e1 + e2 + e3;
            #pragma unroll
            for (int wdt = 1; wdt < 16; wdt <<= 1) {
                rs += __shfl_xor_sync(0xffffffffu, rs, wdt, 16);
            }
            float lold = lrow[row];
            mrow[row] = mc;
            lrow[row] = lold * fsc + rs;
            fac[row]  = fsc;
            *(float4*)&Ss_[row*68 + jg*4] = make_float4(e0, e1, e2, e3);
        }
        __syncthreads();

        // PV: 4q x 4d; j unrolled by 4 with broadcast float4 p loads
        float f0q = fac[qp*4+0], f1q = fac[qp*4+1];
        float f2q = fac[qp*4+2], f3q = fac[qp*4+3];
        #pragma unroll
        for (int u = 0; u < 4; u++) { o[0][u] *= f0q; o[1][u] *= f1q; o[2][u] *= f2q; o[3][u] *= f3q; }
        #pragma unroll 4
        for (int j4 = 0; j4 < 64; j4 += 4) {
            float4 pq0 = *(const float4*)&Ss_[(qp*4+0)*68 + j4];
            float4 pq1 = *(const float4*)&Ss_[(qp*4+1)*68 + j4];
            float4 pq2 = *(const float4*)&Ss_[(qp*4+2)*68 + j4];
            float4 pq3 = *(const float4*)&Ss_[(qp*4+3)*68 + j4];
            #pragma unroll
            for (int jj = 0; jj < 4; jj++) {
                float4 vv = *(const float4*)&Vs_[(j4+jj)*68 + dp];
                float p0 = ((const float*)&pq0)[jj];
                float p1 = ((const float*)&pq1)[jj];
                float p2 = ((const float*)&pq2)[jj];
                float p3 = ((const float*)&pq3)[jj];
                o[0][0] += p0*vv.x; o[0][1] += p0*vv.y; o[0][2] += p0*vv.z; o[0][3] += p0*vv.w;
                o[1][0] += p1*vv.x; o[1][1] += p1*vv.y; o[1][2] += p1*vv.z; o[1][3] += p1*vv.w;
                o[2][0] += p2*vv.x; o[2][1] += p2*vv.y; o[2][2] += p2*vv.z; o[2][3] += p2*vv.w;
                o[3][0] += p3*vv.x; o[3][1] += p3*vv.y; o[3][2] += p3*vv.z; o[3][3] += p3*vv.w;
            }
        }
        __syncthreads();
    }
    #pragma unroll
    for (int i = 0; i < 4; i++) {
        float inv = 1.0f / lrow[qp*4 + i];
        size_t dst = (size_t)(f0 + qp*4 + i)*DOUT + h*HD + dp;
        *(float4*)&Obuf[dst] = make_float4(o[i][0]*inv, o[i][1]*inv, o[i][2]*inv, o[i][3]*inv);
    }
}

// ---------------------------- gate combine -----------------------------------
__global__ void combine_kernel(float* __restrict__ out)
{
    int e = blockIdx.x * 256 + threadIdx.x;
    float w = g_w[e];
    out[e] = w * g_c1[e] + (1.0f - w) * g_c2[e];
}

// ------------------------------- launch --------------------------------------
extern "C" void kernel_launch(void* const* d_in, const int* in_sizes, int n_in,
                              void* d_out, int out_size)
{
    const float* x     = (const float*)d_in[0];
    const float* Wq    = (const float*)d_in[1];
    const float* Wk    = (const float*)d_in[2];
    const float* Wv    = (const float*)d_in[3];
    const float* Ww    = (const float*)d_in[4];
    const float* Wo    = (const float*)d_in[5];
    const float* bo    = (const float*)d_in[6];
    const float* kmem0 = (const float*)d_in[7];
    const float* vmem0 = (const float*)d_in[8];
    float* out = (float*)d_out;

    float *q, *k, *v, *w, *ao, *aom, *c1, *c2, *km, *vm;
    cudaGetSymbolAddress((void**)&q,   g_q);
    cudaGetSymbolAddress((void**)&k,   g_k);
    cudaGetSymbolAddress((void**)&v,   g_v);
    cudaGetSymbolAddress((void**)&w,   g_w);
    cudaGetSymbolAddress((void**)&ao,  g_ao);
    cudaGetSymbolAddress((void**)&aom, g_aom);
    cudaGetSymbolAddress((void**)&c1,  g_c1);
    cudaGetSymbolAddress((void**)&c2,  g_c2);
    cudaGetSymbolAddress((void**)&km,  g_km);
    cudaGetSymbolAddress((void**)&vm,  g_vm);
    __half *xhi, *xlo, *Whi, *Wlo, *ahi, *alo;
    cudaGetSymbolAddress((void**)&xhi, g_xhi);
    cudaGetSymbolAddress((void**)&xlo, g_xlo);
    cudaGetSymbolAddress((void**)&Whi, g_Whi);
    cudaGetSymbolAddress((void**)&Wlo, g_Wlo);
    cudaGetSymbolAddress((void**)&ahi, g_ahi);
    cudaGetSymbolAddress((void**)&alo, g_alo);

    const int SIMS_SMEM  = (64*72 + 128*72)*2 + 64*132*4;   // 61440
    const int FLASH_SMEM = 4*64*72*2 + 2*64*68*4 + 3*64*4;  // 72448
    const int HGEMM_SMEM = 4*128*72*2;                      // 73728
    cudaFuncSetAttribute(sims_topk,  cudaFuncAttributeMaxDynamicSharedMemorySize, SIMS_SMEM);
    cudaFuncSetAttribute(flash_attn, cudaFuncAttributeMaxDynamicSharedMemorySize, FLASH_SMEM);
    cudaFuncSetAttribute(hgemm_abt,  cudaFuncAttributeMaxDynamicSharedMemorySize, HGEMM_SMEM);

    const int WSZ = DIN*DOUT;
    dim3 hgrid(DOUT/128, BNR/128);

    split_f32<<<(BNR*DIN)/256, 256>>>(x,  xhi, xlo);
    split_f32<<<WSZ/256, 256>>>(Wq, Whi + 0*WSZ, Wlo + 0*WSZ);
    split_f32<<<WSZ/256, 256>>>(Wk, Whi + 1*WSZ, Wlo + 1*WSZ);
    split_f32<<<WSZ/256, 256>>>(Wv, Whi + 2*WSZ, Wlo + 2*WSZ);
    split_f32<<<WSZ/256, 256>>>(Ww, Whi + 3*WSZ, Wlo + 3*WSZ);
    split_f32<<<WSZ/256, 256>>>(Wo, Whi + 4*WSZ, Wlo + 4*WSZ);

    hgemm_abt<<<hgrid, 256, HGEMM_SMEM>>>(xhi, xlo, Whi + 0*WSZ, Wlo + 0*WSZ, q, DIN, 0, 0);
    hgemm_abt<<<hgrid, 256, HGEMM_SMEM>>>(xhi, xlo, Whi + 1*WSZ, Wlo + 1*WSZ, k, DIN, 0, 0);
    hgemm_abt<<<hgrid, 256, HGEMM_SMEM>>>(xhi, xlo, Whi + 2*WSZ, Wlo + 2*WSZ, v, DIN, 0, 0);
    hgemm_abt<<<hgrid, 256, HGEMM_SMEM>>>(xhi, xlo, Whi + 3*WSZ, Wlo + 3*WSZ, w, DIN, 0, 1);

    convert_q<<<(H*BNR*HD)/256, 256>>>();
    convert_k<<<(H*MEMS*HD/4)/256, 256>>>(kmem0);

    sims_topk<<<dim3(BNR/64, H), 256, SIMS_SMEM>>>();
    flash_attn<<<dim3(NN/64, H, BB), 256, FLASH_SMEM>>>(q, k, v, ao, NN);
    rescore_kernel<<<(H*BNR)/8, 256>>>(kmem0);
    gather_kernel<<<(BB*NN*IPQ*DIN)/256, 256>>>(kmem0, vmem0);
    flash_attn<<<dim3(NN/64, H, BB), 256, FLASH_SMEM>>>(q, km, vm, aom, NN*IPQ);

    split_f32<<<(BNR*DOUT)/256, 256>>>(ao, ahi, alo);
    hgemm_abt<<<hgrid, 256, HGEMM_SMEM>>>(ahi, alo, Whi + 4*WSZ, Wlo + 4*WSZ, c1, DOUT, bo, 0);
    split_f32<<<(BNR*DOUT)/256, 256>>>(aom, ahi, alo);
    hgemm_abt<<<hgrid, 256, HGEMM_SMEM>>>(ahi, alo, Whi + 4*WSZ, Wlo + 4*WSZ, c2, DOUT, bo, 0);

    combine_kernel<<<(BNR*DOUT)/256, 256>>>(out);
}